// round 14
// baseline (speedup 1.0000x reference)
#include <cuda_runtime.h>

// Problem constants (fixed by the reference setup)
#define DE   200          // entity / output dim
#define DR   200          // relation dim
#define DIN  400          // DE + DR
#define NB   4            // num bases
#define KTOT (NB * DIN)   // 1600 rows of the collapsed matvec

#define NBLK 148          // one wave
#define NTHR 512          // 16 warps
#define NMM  25           // consumer blocks: blockIdx 0..24 (scan-free)
#define NSCAN (NBLK - NMM)      // 123 scan blocks: blockIdx 25..147
#define TARGET (NSCAN + 1)      // arrivals: 123 scan blocks + block 0 (out-zero)
#define KCH  64           // k-rows per consumer block (25*64 = 1600 EXACT)
#define KPG  32           // k-rows per thread-group (2 groups x 256 threads)
#define MAXM 1024         // slot capacity (expected ~8 matches)
#define NSPEC 15          // spec warps 1..15 own slots 0..14

// persistent scratch (static device globals — no allocation).
// g_seq: monotonic launch counter (incremented once per launch by releaser).
// g_arr: double-buffered arrive/count word (low16 arrivals, high16 match
//        count). Buffer seq&1 is used this launch; the releaser zeroes the
//        OTHER buffer for the next launch. Padded to separate cache lines.
// g_slot: self-validating: bits[19:64) = seq+1 tag, bits[0:19) = edge index.
__device__ unsigned           g_seq;
__device__ unsigned           g_arr[2][32];
__device__ unsigned long long g_slot[MAXM];

__global__ void __launch_bounds__(NTHR, 1)
fused_kernel(const float* __restrict__ ent,
             const float* __restrict__ relemb,
             const float* __restrict__ basis,
             const float* __restrict__ att,
             const int*   __restrict__ node_id,
             const int*   __restrict__ edge_src,
             const int*   __restrict__ edge_dst,
             const int*   __restrict__ edge_type,
             const int*   __restrict__ rel_index,
             const int*   __restrict__ u_ptr,
             float* __restrict__ out,
             int E) {
    const int tid  = threadIdx.x;
    const int wid  = tid >> 5;
    const int lane = tid & 31;
    const bool is_mv = (blockIdx.x < NMM);

    const unsigned seq = g_seq;                        // stable this launch
    const unsigned par = seq & 1u;
    const unsigned long long tag = (unsigned long long)(seq + 1u);
    unsigned* arr      = &g_arr[par][0];
    unsigned* arr_next = &g_arr[par ^ 1u][0];

    // releaser duty: the TARGET-th arriver preps state for the next launch
    auto arrive = [&](void) {
        unsigned old = atomicAdd(arr, 1u);
        if ((old & 0xFFFFu) == TARGET - 1) {           // releaser
            *arr_next = 0;                             // next launch's buffer
            __threadfence();
            g_seq = seq + 1u;
        }
    };

    if (!is_mv) {
        // ───────────────────────── scan block ─────────────────────────
        // Finder publishes INSTANTLY: slot = (tag<<19)|e — no loads on the
        // finder path, so scan blocks arrive with zero straggler chain.
        auto found = [&](int e) {
            unsigned old = atomicAdd(arr, 1u << 16);
            unsigned p = old >> 16;
            if (p < MAXM)
                *(volatile unsigned long long*)&g_slot[p] =
                    (tag << 19) | (unsigned long long)(unsigned)e;
        };
        const int sgt = (blockIdx.x - NMM) * NTHR + tid;
        const int SGT = NSCAN * NTHR;
        const int u   = *u_ptr;                        // L1-cached broadcast
        const int nv  = E >> 2;
        const int4* ed4 = (const int4*)edge_dst;
        for (int i = sgt; i < nv; i += 2 * SGT) {      // 2-wide MLP, 1 iter
            int  i2 = i + SGT;
            bool h2 = i2 < nv;
            int4 v1 = __ldcg(&ed4[i]);
            int4 v2;
            if (h2) v2 = __ldcg(&ed4[i2]);
            int b1 = i << 2;
            if (v1.x == u) found(b1 + 0);
            if (v1.y == u) found(b1 + 1);
            if (v1.z == u) found(b1 + 2);
            if (v1.w == u) found(b1 + 3);
            if (h2) {
                int b2 = i2 << 2;
                if (v2.x == u) found(b2 + 0);
                if (v2.y == u) found(b2 + 1);
                if (v2.z == u) found(b2 + 2);
                if (v2.w == u) found(b2 + 3);
            }
        }
        for (int e = (nv << 2) + sgt; e < E; e += SGT) {   // scalar tail
            if (__ldcg(&edge_dst[e]) == u) found(e);
        }
        __syncthreads();
        if (tid == 0) { __threadfence(); arrive(); }
        return;                                        // scan blocks exit
    }

    // ──────────────────────── consumer block (no scan) ────────────────────
    const int k0   = blockIdx.x * KCH;                 // kmax == KCH exactly
    const int g    = tid >> 8;        // 0 or 1
    const int o    = tid & 255;       // output index within group

    __shared__ float        sy[KCH];
    __shared__ float        s1[256];
    __shared__ volatile int s_flag;
    __shared__ volatile int s_cnt;

    // block 0 zeroes the REDG target, then ARRIVES (so low16==TARGET orders
    // the zeroing before every consumer's REDG).
    if (blockIdx.x == 0) {
        if (tid < DE) out[tid] = 0.0f;
        __syncthreads();
        if (tid == 0) { __threadfence(); arrive(); }
    }

    // prefetch basis chunk into registers; zero sy and control flags
    float breg[KPG];
    if (o < DE) {
        #pragma unroll
        for (int j = 0; j < KPG; j++) {
            breg[j] = __ldcg(&basis[(size_t)(k0 + g * KPG + j) * DE + o]);
        }
    }
    if (tid < KCH) sy[tid] = 0.0f;
    if (tid == 0) { s_flag = 0; s_cnt = 0; }
    __syncthreads();

    // ── spec consume: warp w (1..15) polls slot w-1 from t=0; the meta chain
    //    (edge_src -> node_id -> x) runs DURING the scan. Warp 0/tid0 polls
    //    the arrive word and broadcasts completion via smem. ──
    if (wid == 0) {
        if (tid == 0) {
            unsigned v;
            do { v = *(volatile unsigned*)arr; } while ((v & 0xFFFFu) != TARGET);
            __threadfence();                           // acquire
            s_cnt = (int)(v >> 16);
            __threadfence_block();
            s_flag = 1;
        }
    } else {
        const int m = wid - 1;                         // slot owned by warp
        unsigned long long v;
        bool have = false;
        for (;;) {
            v = *(volatile unsigned long long*)&g_slot[m];
            if ((v >> 19) == tag) { have = true; break; }   // self-validating
            if (s_flag && s_cnt <= m) break;           // will never fill
        }
        if (have) {
            int e  = (int)(v & 0x7FFFFu);
            int s  = __ldcg(&edge_src[e]);             // these issue together
            int ri = __ldcg(&rel_index[e]);
            int ty = __ldcg(&edge_type[e]);
            int nid = __ldcg(&node_id[s]);             // serial hop
            const float* arow = att + (size_t)ty * NB;
            #pragma unroll
            for (int h = 0; h < 2; h++) {
                int kk = lane + h * 32;                // covers 0..63 exactly
                int k = k0 + kk;
                int b = k / DIN;
                int i = k - b * DIN;
                float x = (i < DE)
                    ? __ldcg(&ent[(size_t)nid * DE + i])
                    : __ldcg(&relemb[(size_t)ri * DR + (i - DE)]);
                atomicAdd(&sy[kk], arow[b] * x);
            }
        }
    }
    __syncthreads();

    const int   cnt  = s_cnt;
    const int   cntc = cnt < MAXM ? cnt : MAXM;
    const float inv  = 1.0f / fmaxf((float)cnt, 1.0f);

    if (cntc > NSPEC) {                                // rare (expected cnt≈8)
        const int total = (cntc - NSPEC) * KCH;
        for (int p = tid; p < total; p += NTHR) {
            int mm = NSPEC + p / KCH;
            int kk = p - (mm - NSPEC) * KCH;
            unsigned long long v = g_slot[mm];
            int e  = (int)(v & 0x7FFFFu);
            int s  = __ldcg(&edge_src[e]);
            int ri = __ldcg(&rel_index[e]);
            int ty = __ldcg(&edge_type[e]);
            int nid = __ldcg(&node_id[s]);
            int k = k0 + kk;
            int b = k / DIN;
            int i = k - b * DIN;
            float x = (i < DE)
                ? __ldcg(&ent[(size_t)nid * DE + i])
                : __ldcg(&relemb[(size_t)ri * DR + (i - DE)]);
            atomicAdd(&sy[kk], att[ty * NB + b] * x);
        }
        __syncthreads();
    }

    // combine halves in smem -> ONE REDG lane per output element, pre-scaled
    float acc = 0.0f;
    if (o < DE) {
        #pragma unroll
        for (int j = 0; j < KPG; j++) acc += sy[g * KPG + j] * breg[j];
        if (g == 1) s1[o] = acc;
    }
    __syncthreads();
    if (o < DE && g == 0 && cntc > 0) {
        atomicAdd(&out[o], (acc + s1[o]) * inv);       // fire-and-forget REDG
    }
    // no reset tail: arrive buffer for the next launch zeroed by the
    // releaser; g_seq monotonic; slots invalidated by the seq tag.
}

extern "C" void kernel_launch(void* const* d_in, const int* in_sizes, int n_in,
                              void* d_out, int out_size) {
    const float* ent    = (const float*)d_in[0];  // [100000, 200]
    const float* relemb = (const float*)d_in[1];  // [200, 200]
    const float* basis  = (const float*)d_in[2];  // [4, 400, 200]
    const float* att    = (const float*)d_in[3];  // [400, 4]
    const int* node_id  = (const int*)d_in[4];    // [50000]
    const int* edge_src = (const int*)d_in[5];    // [400000]
    const int* edge_dst = (const int*)d_in[6];    // [400000]
    const int* edge_typ = (const int*)d_in[7];    // [400000]
    const int* rel_idx  = (const int*)d_in[8];    // [400000]
    const int* u_ptr    = (const int*)d_in[9];    // scalar
    float* out = (float*)d_out;                   // [200]

    int E = in_sizes[6];

    fused_kernel<<<NBLK, NTHR>>>(ent, relemb, basis, att,
                                 node_id, edge_src, edge_dst, edge_typ, rel_idx,
                                 u_ptr, out, E);
}

// round 15
// speedup vs baseline: 1.0294x; 1.0294x over previous
#include <cuda_runtime.h>

// Problem constants (fixed by the reference setup)
#define DE   200          // entity / output dim
#define DR   200          // relation dim
#define DIN  400          // DE + DR
#define NB   4            // num bases
#define KTOT (NB * DIN)   // 1600 rows of the collapsed matvec

#define NBLK 148          // one wave
#define NTHR 512          // 16 warps
#define NMM  25           // consumer blocks (scan-free)
#define NSCAN (NBLK - NMM)   // 123 scan blocks: blockIdx 0..122 (EARLIEST dispatch)
#define TARGET NSCAN         // arrivals: 123 scan blocks (block 0 also zeroes out)
#define KCH  64           // k-rows per consumer block (25*64 = 1600 EXACT)
#define KPG  32           // k-rows per thread-group (2 groups x 256 threads)
#define MAXM 1024         // slot capacity (expected ~8 matches)
#define NSPEC 15          // spec warps 1..15 own slots 0..14

// persistent scratch (static device globals — no allocation).
// g_seq: monotonic launch counter (incremented once per launch by releaser).
// g_arr: double-buffered arrive/count word (low16 arrivals, high16 match
//        count). Buffer seq&1 is used this launch; the releaser zeroes the
//        OTHER buffer for the next launch. Padded to separate cache lines.
// g_slot: self-validating: bits[19:64) = seq+1 tag, bits[0:19) = edge index.
__device__ unsigned           g_seq;
__device__ unsigned           g_arr[2][32];
__device__ unsigned long long g_slot[MAXM];

__global__ void __launch_bounds__(NTHR, 1)
fused_kernel(const float* __restrict__ ent,
             const float* __restrict__ relemb,
             const float* __restrict__ basis,
             const float* __restrict__ att,
             const int*   __restrict__ node_id,
             const int*   __restrict__ edge_src,
             const int*   __restrict__ edge_dst,
             const int*   __restrict__ edge_type,
             const int*   __restrict__ rel_index,
             const int*   __restrict__ u_ptr,
             float* __restrict__ out,
             int E) {
    const int tid  = threadIdx.x;
    const int wid  = tid >> 5;
    const int lane = tid & 31;
    const bool is_scan = (blockIdx.x < NSCAN);   // scanners get EARLIEST slots

    const unsigned seq = g_seq;                        // stable this launch
    const unsigned par = seq & 1u;
    const unsigned long long tag = (unsigned long long)(seq + 1u);
    unsigned* arr      = &g_arr[par][0];
    unsigned* arr_next = &g_arr[par ^ 1u][0];

    if (is_scan) {
        // ───────────────────────── scan block ─────────────────────────
        // Scan block 0 (dispatched FIRST) also zeroes the REDG target;
        // its arrival fence publishes the zeroing before the release.
        if (blockIdx.x == 0 && tid < DE) out[tid] = 0.0f;

        // Finder publishes INSTANTLY: slot = (tag<<19)|e — no loads on the
        // finder path, so scan blocks arrive with zero straggler chain.
        auto found = [&](int e) {
            unsigned old = atomicAdd(arr, 1u << 16);
            unsigned p = old >> 16;
            if (p < MAXM)
                *(volatile unsigned long long*)&g_slot[p] =
                    (tag << 19) | (unsigned long long)(unsigned)e;
        };
        const int sgt = blockIdx.x * NTHR + tid;
        const int SGT = NSCAN * NTHR;
        const int u   = *u_ptr;                        // L1-cached broadcast
        const int nv  = E >> 2;
        const int4* ed4 = (const int4*)edge_dst;
        for (int i = sgt; i < nv; i += 2 * SGT) {      // 2-wide MLP, 1 iter
            int  i2 = i + SGT;
            bool h2 = i2 < nv;
            int4 v1 = __ldcg(&ed4[i]);
            int4 v2;
            if (h2) v2 = __ldcg(&ed4[i2]);
            int b1 = i << 2;
            if (v1.x == u) found(b1 + 0);
            if (v1.y == u) found(b1 + 1);
            if (v1.z == u) found(b1 + 2);
            if (v1.w == u) found(b1 + 3);
            if (h2) {
                int b2 = i2 << 2;
                if (v2.x == u) found(b2 + 0);
                if (v2.y == u) found(b2 + 1);
                if (v2.z == u) found(b2 + 2);
                if (v2.w == u) found(b2 + 3);
            }
        }
        for (int e = (nv << 2) + sgt; e < E; e += SGT) {   // scalar tail
            if (__ldcg(&edge_dst[e]) == u) found(e);
        }
        __syncthreads();
        if (tid == 0) {
            __threadfence();                           // publish finds + zero
            unsigned old = atomicAdd(arr, 1u);
            if ((old & 0xFFFFu) == TARGET - 1) {       // releaser
                *arr_next = 0;                         // next launch's buffer
                __threadfence();
                g_seq = seq + 1u;
            }
        }
        return;                                        // scan blocks exit
    }

    // ──────────────────── consumer block (dispatched LAST) ────────────────
    const int cidx = blockIdx.x - NSCAN;               // 0..24
    const int k0   = cidx * KCH;                       // kmax == KCH exactly
    const int g    = tid >> 8;        // 0 or 1
    const int o    = tid & 255;       // output index within group

    __shared__ float        sy[KCH];
    __shared__ float        s1[256];
    __shared__ volatile int s_flag;
    __shared__ volatile int s_cnt;

    // prefetch basis chunk into registers; zero sy and control flags
    float breg[KPG];
    if (o < DE) {
        #pragma unroll
        for (int j = 0; j < KPG; j++) {
            breg[j] = __ldcg(&basis[(size_t)(k0 + g * KPG + j) * DE + o]);
        }
    }
    if (tid < KCH) sy[tid] = 0.0f;
    if (tid == 0) { s_flag = 0; s_cnt = 0; }
    __syncthreads();

    // ── spec consume: warp w (1..15) polls slot w-1 from t=0; the meta chain
    //    (edge_src -> node_id -> x) runs DURING the scan. Warp 0/tid0 polls
    //    the arrive word and broadcasts completion via smem. ──
    if (wid == 0) {
        if (tid == 0) {
            unsigned v;
            do { v = *(volatile unsigned*)arr; } while ((v & 0xFFFFu) != TARGET);
            __threadfence();                           // acquire
            s_cnt = (int)(v >> 16);
            __threadfence_block();
            s_flag = 1;
        }
    } else {
        const int m = wid - 1;                         // slot owned by warp
        unsigned long long v;
        bool have = false;
        for (;;) {
            v = *(volatile unsigned long long*)&g_slot[m];
            if ((v >> 19) == tag) { have = true; break; }   // self-validating
            if (s_flag && s_cnt <= m) break;           // will never fill
        }
        if (have) {
            int e  = (int)(v & 0x7FFFFu);
            int s  = __ldcg(&edge_src[e]);             // these issue together
            int ri = __ldcg(&rel_index[e]);
            int ty = __ldcg(&edge_type[e]);
            int nid = __ldcg(&node_id[s]);             // serial hop
            const float* arow = att + (size_t)ty * NB;
            #pragma unroll
            for (int h = 0; h < 2; h++) {
                int kk = lane + h * 32;                // covers 0..63 exactly
                int k = k0 + kk;
                int b = k / DIN;
                int i = k - b * DIN;
                float x = (i < DE)
                    ? __ldcg(&ent[(size_t)nid * DE + i])
                    : __ldcg(&relemb[(size_t)ri * DR + (i - DE)]);
                atomicAdd(&sy[kk], arow[b] * x);
            }
        }
    }
    __syncthreads();

    const int   cnt  = s_cnt;
    const int   cntc = cnt < MAXM ? cnt : MAXM;
    const float inv  = 1.0f / fmaxf((float)cnt, 1.0f);

    if (cntc > NSPEC) {                                // rare (expected cnt≈8)
        const int total = (cntc - NSPEC) * KCH;
        for (int p = tid; p < total; p += NTHR) {
            int mm = NSPEC + p / KCH;
            int kk = p - (mm - NSPEC) * KCH;
            unsigned long long v = g_slot[mm];
            int e  = (int)(v & 0x7FFFFu);
            int s  = __ldcg(&edge_src[e]);
            int ri = __ldcg(&rel_index[e]);
            int ty = __ldcg(&edge_type[e]);
            int nid = __ldcg(&node_id[s]);
            int k = k0 + kk;
            int b = k / DIN;
            int i = k - b * DIN;
            float x = (i < DE)
                ? __ldcg(&ent[(size_t)nid * DE + i])
                : __ldcg(&relemb[(size_t)ri * DR + (i - DE)]);
            atomicAdd(&sy[kk], att[ty * NB + b] * x);
        }
        __syncthreads();
    }

    // combine halves in smem -> ONE REDG lane per output element, pre-scaled
    float acc = 0.0f;
    if (o < DE) {
        #pragma unroll
        for (int j = 0; j < KPG; j++) acc += sy[g * KPG + j] * breg[j];
        if (g == 1) s1[o] = acc;
    }
    __syncthreads();
    if (o < DE && g == 0 && cntc > 0) {
        atomicAdd(&out[o], (acc + s1[o]) * inv);       // fire-and-forget REDG
    }
    // no reset tail: arrive buffer for the next launch zeroed by the
    // releaser; g_seq monotonic; slots invalidated by the seq tag.
}

extern "C" void kernel_launch(void* const* d_in, const int* in_sizes, int n_in,
                              void* d_out, int out_size) {
    const float* ent    = (const float*)d_in[0];  // [100000, 200]
    const float* relemb = (const float*)d_in[1];  // [200, 200]
    const float* basis  = (const float*)d_in[2];  // [4, 400, 200]
    const float* att    = (const float*)d_in[3];  // [400, 4]
    const int* node_id  = (const int*)d_in[4];    // [50000]
    const int* edge_src = (const int*)d_in[5];    // [400000]
    const int* edge_dst = (const int*)d_in[6];    // [400000]
    const int* edge_typ = (const int*)d_in[7];    // [400000]
    const int* rel_idx  = (const int*)d_in[8];    // [400000]
    const int* u_ptr    = (const int*)d_in[9];    // scalar
    float* out = (float*)d_out;                   // [200]

    int E = in_sizes[6];

    fused_kernel<<<NBLK, NTHR>>>(ent, relemb, basis, att,
                                 node_id, edge_src, edge_dst, edge_typ, rel_idx,
                                 u_ptr, out, E);
}